// round 6
// baseline (speedup 1.0000x reference)
#include <cuda_runtime.h>
#include <cuda_bf16.h>

// SumGoalHistory: out_t = sigmoid(init + prefix_sum(goal, axis=T)), final x2.
// goal [512, 64, 1024] fp32. One thread per column (scalar), 65536 threads =
// 2048 warps (~14/SM) for latency hiding; rotating register buffer NB=32
// (consume-then-refill, prefetch distance 32) keeps ~8.4 MB in flight.

#define T_DIM 512
#define BD    (64 * 1024)
#define NB    32

__device__ __forceinline__ float fast_sigmoid(float x) {
    float t;
    asm("tanh.approx.f32 %0, %1;" : "=f"(t) : "f"(0.5f * x));
    return fmaf(0.5f, t, 0.5f);
}

__global__ __launch_bounds__(64)
void SumGoalHistory_19387482374813_kernel(const float* __restrict__ goal,
                                          const float* __restrict__ init_state,
                                          float* __restrict__ out) {
    const int col = blockIdx.x * blockDim.x + threadIdx.x;  // 0 .. BD-1

    float acc = init_state[col];
    const float* g = goal + col;
    float*       o = out  + col;

    float buf[NB];
    // Prologue: 32 independent loads in flight.
    #pragma unroll
    for (int u = 0; u < NB; u++)
        buf[u] = __ldcs(g + (size_t)u * BD);

    // Main loop: consume buf[u], immediately refill from t0+NB+u.
    for (int t0 = 0; t0 < T_DIM - NB; t0 += NB) {
        #pragma unroll
        for (int u = 0; u < NB; u++) {
            float v = buf[u];
            buf[u] = __ldcs(g + (size_t)(t0 + NB + u) * BD);
            acc += v;
            __stcs(o + (size_t)(t0 + u) * BD, fast_sigmoid(acc));
        }
    }

    // Epilogue: last NB elements, no refill.
    #pragma unroll
    for (int u = 0; u < NB; u++) {
        acc += buf[u];
        __stcs(o + (size_t)(T_DIM - NB + u) * BD, fast_sigmoid(acc));
    }

    // final_state written twice after the outputs block
    __stcs(o + (size_t)T_DIM * BD,       acc);
    __stcs(o + (size_t)(T_DIM + 1) * BD, acc);
}

extern "C" void kernel_launch(void* const* d_in, const int* in_sizes, int n_in,
                              void* d_out, int out_size) {
    const float* goal = (const float*)d_in[0];
    const float* init = (const float*)d_in[1];
    float* out = (float*)d_out;

    SumGoalHistory_19387482374813_kernel<<<BD / 64, 64>>>(goal, init, out);
}

// round 7
// speedup vs baseline: 1.1161x; 1.1161x over previous
#include <cuda_runtime.h>
#include <cuda_bf16.h>

// SumGoalHistory: out_t = sigmoid(init + prefix_sum(goal, axis=T)), final x2.
// goal [512, 64, 1024] fp32. One thread per 4 columns (float4) -> minimal
// LSU issue cost (128 LDG.128 + 128 STG.128 per thread). Rotating register
// buffer NB=32 float4 keeps ~8.4 MB in flight chip-wide (the R4 sweet spot)
// while paying half of R4's memory-instruction issue cycles.

#define T_DIM 512
#define BD    (64 * 1024)
#define NCOL4 (BD / 4)     // 16384 float4 columns
#define NB    32

__device__ __forceinline__ float fast_sigmoid(float x) {
    float t;
    asm("tanh.approx.f32 %0, %1;" : "=f"(t) : "f"(0.5f * x));
    return fmaf(0.5f, t, 0.5f);
}

__global__ __launch_bounds__(64)
void SumGoalHistory_19387482374813_kernel(const float4* __restrict__ goal,
                                          const float4* __restrict__ init_state,
                                          float4* __restrict__ out) {
    const int col = blockIdx.x * blockDim.x + threadIdx.x;  // 0 .. NCOL4-1

    float4 acc = init_state[col];
    const float4* g = goal + col;
    float4*       o = out  + col;

    float4 buf[NB];
    // Prologue: 32 independent LDG.128 in flight.
    #pragma unroll
    for (int u = 0; u < NB; u++)
        buf[u] = __ldcs(g + (size_t)u * NCOL4);

    // Main loop: consume buf[u], immediately refill from t0+NB+u.
    for (int t0 = 0; t0 < T_DIM - NB; t0 += NB) {
        #pragma unroll
        for (int u = 0; u < NB; u++) {
            float4 v = buf[u];
            buf[u] = __ldcs(g + (size_t)(t0 + NB + u) * NCOL4);
            acc.x += v.x;  acc.y += v.y;  acc.z += v.z;  acc.w += v.w;
            float4 s = make_float4(fast_sigmoid(acc.x), fast_sigmoid(acc.y),
                                   fast_sigmoid(acc.z), fast_sigmoid(acc.w));
            __stcs(o + (size_t)(t0 + u) * NCOL4, s);
        }
    }

    // Epilogue: last NB elements, no refill.
    #pragma unroll
    for (int u = 0; u < NB; u++) {
        float4 v = buf[u];
        acc.x += v.x;  acc.y += v.y;  acc.z += v.z;  acc.w += v.w;
        float4 s = make_float4(fast_sigmoid(acc.x), fast_sigmoid(acc.y),
                               fast_sigmoid(acc.z), fast_sigmoid(acc.w));
        __stcs(o + (size_t)(T_DIM - NB + u) * NCOL4, s);
    }

    // final_state written twice after the outputs block
    __stcs(o + (size_t)T_DIM * NCOL4,       acc);
    __stcs(o + (size_t)(T_DIM + 1) * NCOL4, acc);
}

extern "C" void kernel_launch(void* const* d_in, const int* in_sizes, int n_in,
                              void* d_out, int out_size) {
    const float4* goal = (const float4*)d_in[0];
    const float4* init = (const float4*)d_in[1];
    float4* out = (float4*)d_out;

    SumGoalHistory_19387482374813_kernel<<<NCOL4 / 64, 64>>>(goal, init, out);
}

// round 8
// speedup vs baseline: 1.1641x; 1.0430x over previous
#include <cuda_runtime.h>
#include <cuda_bf16.h>

// SumGoalHistory: out_t = sigmoid(init + prefix_sum(goal, axis=T)), final x2.
// goal [512, 64, 1024] fp32. One thread per 2 columns (float2), rotating
// register buffer NB=32 (consume-then-refill, prefetch distance 32) -> 8.4 MB
// in flight chip-wide. 32-thread CTAs (1024 blocks) so per-SM CTA count
// quantizes at 7-vs-6.9 (1.2% tail) instead of R4's 4-vs-3.46 (16% tail).

#define T_DIM 512
#define BD    (64 * 1024)
#define NCOL2 (BD / 2)     // 32768 float2 columns
#define NB    32

__device__ __forceinline__ float fast_sigmoid(float x) {
    float t;
    asm("tanh.approx.f32 %0, %1;" : "=f"(t) : "f"(0.5f * x));
    return fmaf(0.5f, t, 0.5f);
}

__global__ __launch_bounds__(32)
void SumGoalHistory_19387482374813_kernel(const float2* __restrict__ goal,
                                          const float2* __restrict__ init_state,
                                          float2* __restrict__ out) {
    const int col = blockIdx.x * blockDim.x + threadIdx.x;  // 0 .. NCOL2-1

    float2 acc = init_state[col];
    const float2* g = goal + col;
    float2*       o = out  + col;

    float2 buf[NB];
    // Prologue: 32 independent LDG.64 in flight.
    #pragma unroll
    for (int u = 0; u < NB; u++)
        buf[u] = __ldcs(g + (size_t)u * NCOL2);

    // Main loop: consume buf[u], immediately refill from t0+NB+u.
    for (int t0 = 0; t0 < T_DIM - NB; t0 += NB) {
        #pragma unroll
        for (int u = 0; u < NB; u++) {
            float2 v = buf[u];
            buf[u] = __ldcs(g + (size_t)(t0 + NB + u) * NCOL2);
            acc.x += v.x;
            acc.y += v.y;
            float2 s = make_float2(fast_sigmoid(acc.x), fast_sigmoid(acc.y));
            __stcs(o + (size_t)(t0 + u) * NCOL2, s);
        }
    }

    // Epilogue: last NB elements, no refill.
    #pragma unroll
    for (int u = 0; u < NB; u++) {
        acc.x += buf[u].x;
        acc.y += buf[u].y;
        float2 s = make_float2(fast_sigmoid(acc.x), fast_sigmoid(acc.y));
        __stcs(o + (size_t)(T_DIM - NB + u) * NCOL2, s);
    }

    // final_state written twice after the outputs block
    __stcs(o + (size_t)T_DIM * NCOL2,       acc);
    __stcs(o + (size_t)(T_DIM + 1) * NCOL2, acc);
}

extern "C" void kernel_launch(void* const* d_in, const int* in_sizes, int n_in,
                              void* d_out, int out_size) {
    const float2* goal = (const float2*)d_in[0];
    const float2* init = (const float2*)d_in[1];
    float2* out = (float2*)d_out;

    SumGoalHistory_19387482374813_kernel<<<NCOL2 / 32, 32>>>(goal, init, out);
}